// round 14
// baseline (speedup 1.0000x reference)
#include <cuda_runtime.h>
#include <cuda_fp16.h>
#include <stdint.h>

// Problem constants (fixed by the dataset)
#define BB   16
#define NN   2048
#define CC   256
#define KK   16
#define KP1  17
#define OUTC 259   // 3 + C

// Scratch for knn indices (device global: allocation-free)
__device__ int g_knn[BB * NN * KK];

// order-preserving fp32 -> u32 map
__device__ __forceinline__ unsigned f2u(float f) {
    unsigned u = __float_as_uint(f);
    return u ^ (((unsigned)((int)u >> 31)) | 0x80000000u);
}

#define FULL 0xffffffffu

// ---------------------------------------------------------------------------
// Kernel A: TWO warps per query, exact top-17.
// Warp pair (even, odd) handles one query: even scans m in [0,1024), odd scans
// [1024,2048); each keeps its half's top-17 one-per-lane (lanes 0..16) with
// the R10 REDUX insert (ascending-m processing + strict accept => exact lex
// (d2,idx) semantics within the half). Odd warp publishes its 17 pairs via
// smem; even warp merges them with an ORDER-INDEPENDENT lex compare:
// accept iff (cu,ci) < (maxu,emx); evict the lex-largest holder. The merged
// list is the exact global top-17 under (d2,idx) lex order == jax top_k.
// ---------------------------------------------------------------------------
#define QPB 4   // queries per block (4 pairs = 8 warps = 256 threads)
#define HALF (NN / 2)

__global__ __launch_bounds__(256)
void knn_kernel(const float* __restrict__ xyz, float* __restrict__ out)
{
    __shared__ float4 sp[NN];              // 32 KB: x, y, z, |p|^2
    __shared__ uint2  mb[QPB][KP1];        // odd-warp lists (544 B)

    const int b    = blockIdx.y;
    const int tid  = threadIdx.x;
    const int lane = tid & 31;
    const int warp = tid >> 5;
    const int pair = warp >> 1;            // 0..3
    const int half = warp & 1;             // 0 = low half, 1 = high half
    const float* xb = xyz + (size_t)b * NN * 3;

    for (int m = tid; m < NN; m += 256) {
        float x = xb[m * 3 + 0];
        float y = xb[m * 3 + 1];
        float z = xb[m * 3 + 2];
        sp[m] = make_float4(x, y, z, x * x + y * y + z * z);
    }
    __syncthreads();

    const int n = blockIdx.x * QPB + pair; // this pair's query
    const float4 q = sp[n];

    const bool holder = (lane < KP1);
    // distinct huge sentinels (real u keys are far below 0xFFFFFF00)
    unsigned ku   = holder ? (0xFFFFFF00u | (unsigned)lane) : 0u;
    unsigned kidx = 0u;
    unsigned maxu = 0xFFFFFF00u | (KP1 - 1);

    const int base = half * HALF;
    for (int step = 0; step < HALF / 64; step++) {
        const int m0 = base + step * 64 + lane;
        float4 p0 = sp[m0];
        float4 p1 = sp[m0 + 32];
        float dot0 = q.x * p0.x + q.y * p0.y + q.z * p0.z;
        float dot1 = q.x * p1.x + q.y * p1.y + q.z * p1.z;
        float d20  = q.w + p0.w - 2.0f * dot0;   // same formula as reference
        float d21  = q.w + p1.w - 2.0f * dot1;
        unsigned u0 = f2u(d20);
        unsigned u1 = f2u(d21);

        unsigned bal0 = __ballot_sync(FULL, u0 < maxu);
        unsigned bal1 = __ballot_sync(FULL, u1 < maxu);

        while (bal0) {                        // ascending m within group 0
            const int src = __ffs(bal0) - 1;
            bal0 &= bal0 - 1;
            unsigned cu = __shfl_sync(FULL, u0, src);
            unsigned cm = (unsigned)(base + step * 64 + src);
            if (cu < maxu) {                  // strict: boundary tie -> reject
                bool ismax = holder && (ku == maxu);
                unsigned emx = __reduce_max_sync(FULL, ismax ? kidx : 0u);
                if (ismax && kidx == emx) { ku = cu; kidx = cm; }
                maxu = __reduce_max_sync(FULL, holder ? ku : 0u);
            }
        }
        while (bal1) {                        // then group 1 (m0+32)
            const int src = __ffs(bal1) - 1;
            bal1 &= bal1 - 1;
            unsigned cu = __shfl_sync(FULL, u1, src);
            unsigned cm = (unsigned)(base + step * 64 + 32 + src);
            if (cu < maxu) {
                bool ismax = holder && (ku == maxu);
                unsigned emx = __reduce_max_sync(FULL, ismax ? kidx : 0u);
                if (ismax && kidx == emx) { ku = cu; kidx = cm; }
                maxu = __reduce_max_sync(FULL, holder ? ku : 0u);
            }
        }
    }

    // odd warp publishes its half-list
    if (half == 1 && holder) mb[pair][lane] = make_uint2(ku, kidx);
    __syncthreads();

    if (half == 1) return;    // even warp finishes the query

    // current lex-largest holder (maxu, emx)
    bool ismax = holder && (ku == maxu);
    unsigned emx = __reduce_max_sync(FULL, ismax ? kidx : 0u);

    // merge odd-half entries: order-independent lex compare (no tie hazard)
    unsigned cu_l = 0xFFFFFFFFu, ci_l = 0xFFFFFFFFu;
    if (holder) { uint2 e = mb[pair][lane]; cu_l = e.x; ci_l = e.y; }
    unsigned bal = __ballot_sync(FULL,
        (cu_l < maxu) || (cu_l == maxu && ci_l < emx));
    while (bal) {
        const int src = __ffs(bal) - 1;
        bal &= bal - 1;
        unsigned cu = __shfl_sync(FULL, cu_l, src);
        unsigned ci = __shfl_sync(FULL, ci_l, src);
        if ((cu < maxu) || (cu == maxu && ci < emx)) {
            if (holder && ku == maxu && kidx == emx) { ku = cu; kidx = ci; }
            maxu = __reduce_max_sync(FULL, holder ? ku : 0u);
            ismax = holder && (ku == maxu);
            emx  = __reduce_max_sync(FULL, ismax ? kidx : 0u);
        }
    }

    // identify self = lex-min (sorted column 0 in the reference) -> drop
    unsigned minu = __reduce_min_sync(FULL, holder ? ku : 0xFFFFFFFFu);
    bool ismin = holder && (ku == minu);
    unsigned mni = __reduce_min_sync(FULL, ismin ? kidx : 0xFFFFFFFFu);
    bool keep = holder && !(ismin && kidx == mni);

    // mean of neighbor xyz (16 keepers)
    float4 pN = make_float4(0.f, 0.f, 0.f, 0.f);
    if (keep) pN = sp[kidx];
    float sx = pN.x, sy = pN.y, sz = pN.z;
#pragma unroll
    for (int o = 16; o > 0; o >>= 1) {
        sx += __shfl_xor_sync(FULL, sx, o);
        sy += __shfl_xor_sync(FULL, sy, o);
        sz += __shfl_xor_sync(FULL, sz, o);
    }
    if (lane == 0) {
        const float inv = 1.0f / (float)KK;
        size_t ob = ((size_t)b * NN + n) * OUTC;
        out[ob + 0] = sx * inv - q.x;
        out[ob + 1] = sy * inv - q.y;
        out[ob + 2] = sz * inv - q.z;
    }

    // emit knn indices (order within row irrelevant: gather sums them)
    unsigned kb = __ballot_sync(FULL, keep);
    int pos = __popc(kb & ((1u << lane) - 1u));
    if (keep) g_knn[((size_t)b * NN + n) * KK + pos] = (int)kidx;
}

// ---------------------------------------------------------------------------
// Kernel B: feature gather + mean - self, fp16x2 channel pairing (R12 exact).
// Block covers 32 channels: SMEM row c (0..15) holds half2(ch c0+c, ch c0+c+16)
// for all 2048 points, pitch 2049 -> the 16 channel lanes of a group hit banks
// (c + idx) % 32, conflict-free. One LDS gather feeds TWO output channels.
// ---------------------------------------------------------------------------
#define CTP    32           // channels per block (16 half2 rows)
#define PITCH  2049
#define SMEMB  (16 * PITCH * (int)sizeof(__half2))

__global__ __launch_bounds__(1024)
void gather_kernel(const float* __restrict__ features, float* __restrict__ out)
{
    extern __shared__ __half2 fsm[];   // [16][PITCH]

    const int b   = blockIdx.y;
    const int c0  = blockIdx.x * CTP;
    const int tid = threadIdx.x;

    // Stage: pack channels (c0+c, c0+c+16) as half2 rows
    const float* fbase = features + ((size_t)b * CC + c0) * NN;
    for (int i = tid; i < 16 * NN; i += 1024) {
        int c = i >> 11;          // 0..15
        int m = i & (NN - 1);
        float v0 = fbase[(size_t)c * NN + m];
        float v1 = fbase[(size_t)(c + 16) * NN + m];
        fsm[c * PITCH + m] = __floats2half2_rn(v0, v1);
    }
    __syncthreads();

    const int c  = tid & 15;      // half2 row
    const int n0 = tid >> 4;      // 0..63

    const int*     knn_b = g_knn + (size_t)b * NN * KK;
    const __half2* frow  = fsm + c * PITCH;
    float* outc = out + (size_t)b * NN * OUTC + 3 + c0 + c;

#pragma unroll 2
    for (int n = n0; n < NN; n += 64) {
        const int4* kr = (const int4*)(knn_b + n * KK);
        int4 k0 = __ldg(kr + 0);
        int4 k1 = __ldg(kr + 1);
        int4 k2 = __ldg(kr + 2);
        int4 k3 = __ldg(kr + 3);

        float2 a0 = __half22float2(frow[k0.x]);
        float2 a1 = __half22float2(frow[k0.y]);
        float2 a2 = __half22float2(frow[k0.z]);
        float2 a3 = __half22float2(frow[k0.w]);
        float2 a4 = __half22float2(frow[k1.x]);
        float2 a5 = __half22float2(frow[k1.y]);
        float2 a6 = __half22float2(frow[k1.z]);
        float2 a7 = __half22float2(frow[k1.w]);
        float s0 = a0.x + a1.x + a2.x + a3.x + a4.x + a5.x + a6.x + a7.x;
        float s1 = a0.y + a1.y + a2.y + a3.y + a4.y + a5.y + a6.y + a7.y;
        a0 = __half22float2(frow[k2.x]);
        a1 = __half22float2(frow[k2.y]);
        a2 = __half22float2(frow[k2.z]);
        a3 = __half22float2(frow[k2.w]);
        a4 = __half22float2(frow[k3.x]);
        a5 = __half22float2(frow[k3.y]);
        a6 = __half22float2(frow[k3.z]);
        a7 = __half22float2(frow[k3.w]);
        s0 += a0.x + a1.x + a2.x + a3.x + a4.x + a5.x + a6.x + a7.x;
        s1 += a0.y + a1.y + a2.y + a3.y + a4.y + a5.y + a6.y + a7.y;

        float2 self = __half22float2(frow[n]);
        float* o = outc + (size_t)n * OUTC;
        o[0]  = s0 * (1.0f / (float)KK) - self.x;
        o[16] = s1 * (1.0f / (float)KK) - self.y;
    }
}

// ---------------------------------------------------------------------------
extern "C" void kernel_launch(void* const* d_in, const int* in_sizes, int n_in,
                              void* d_out, int out_size)
{
    const float* xyz      = (const float*)d_in[0];
    const float* features = (const float*)d_in[1];
    float* out = (float*)d_out;

    knn_kernel<<<dim3(NN / QPB, BB), 256>>>(xyz, out);

    cudaFuncSetAttribute(gather_kernel,
                         cudaFuncAttributeMaxDynamicSharedMemorySize, SMEMB);
    gather_kernel<<<dim3(CC / CTP, BB), 1024, SMEMB>>>(features, out);
}

// round 15
// speedup vs baseline: 1.5593x; 1.5593x over previous
#include <cuda_runtime.h>
#include <cuda_fp16.h>
#include <stdint.h>

// Problem constants (fixed by the dataset)
#define BB   16
#define NN   2048
#define CC   256
#define KK   16
#define KP1  17
#define OUTC 259   // 3 + C

// Scratch for knn indices (device global: allocation-free)
__device__ int g_knn[BB * NN * KK];

// order-preserving fp32 -> u32 map
__device__ __forceinline__ unsigned f2u(float f) {
    unsigned u = __float_as_uint(f);
    return u ^ (((unsigned)((int)u >> 31)) | 0x80000000u);
}

#define FULL 0xffffffffu

// ---------------------------------------------------------------------------
// Kernel A: warp-per-query exact top-17 (R12 structure, 16 queries/block).
// Ranking key: d2' = |p|^2 - 2 q.p  (the per-query constant |q|^2 is dropped;
// it cannot change per-query ordering). 17 best (u32 sortable key, idx) live
// one-per-lane on lanes 0..16. Each iteration scans 64 candidates (2/lane);
// ballots processed serially in ascending m, warp-uniform. Eviction: among
// holders with key == max, evict largest idx (top_k tie semantics); strict
// accept keeps incumbents on boundary ties. (key, idx) unique -> single
// eviction always. Self = lex-min pair == reference's sorted column 0.
// ---------------------------------------------------------------------------
#define QW 16   // queries (warps) per block -> 512 threads
__global__ __launch_bounds__(512)
void knn_kernel(const float* __restrict__ xyz, float* __restrict__ out)
{
    __shared__ float4 sp[NN];   // 32 KB: x, y, z, |p|^2

    const int b    = blockIdx.y;
    const int tid  = threadIdx.x;
    const int lane = tid & 31;
    const int warp = tid >> 5;
    const float* xb = xyz + (size_t)b * NN * 3;

    for (int m = tid; m < NN; m += 512) {
        float x = xb[m * 3 + 0];
        float y = xb[m * 3 + 1];
        float z = xb[m * 3 + 2];
        sp[m] = make_float4(x, y, z, x * x + y * y + z * z);
    }
    __syncthreads();

    const int n = blockIdx.x * QW + warp;     // this warp's query
    const float4 q = sp[n];

    const bool holder = (lane < KP1);
    // distinct huge sentinels (real u keys are far below 0xFFFFFF00)
    unsigned ku   = holder ? (0xFFFFFF00u | (unsigned)lane) : 0u;
    unsigned kidx = 0u;
    unsigned maxu = 0xFFFFFF00u | (KP1 - 1);  // current 17th (max of holders)

    for (int step = 0; step < NN / 64; step++) {
        const int m0 = step * 64 + lane;
        float4 p0 = sp[m0];                   // 2 independent LDS.128 chains
        float4 p1 = sp[m0 + 32];
        float dot0 = p0.x * q.x + p0.y * q.y + p0.z * q.z;
        float dot1 = p1.x * q.x + p1.y * q.y + p1.z * q.z;
        float d20  = fmaf(-2.0f, dot0, p0.w); // |p|^2 - 2 q.p (constant shift)
        float d21  = fmaf(-2.0f, dot1, p1.w);
        unsigned u0 = f2u(d20);
        unsigned u1 = f2u(d21);

        unsigned bal0 = __ballot_sync(FULL, u0 < maxu);
        unsigned bal1 = __ballot_sync(FULL, u1 < maxu);

        while (bal0) {                        // ascending m within group 0
            const int src = __ffs(bal0) - 1;
            bal0 &= bal0 - 1;
            unsigned cu = __shfl_sync(FULL, u0, src);
            unsigned cm = (unsigned)(step * 64 + src);
            if (cu < maxu) {                  // strict: boundary tie -> reject
                bool ismax = holder && (ku == maxu);
                unsigned emx = __reduce_max_sync(FULL, ismax ? kidx : 0u);
                if (ismax && kidx == emx) { ku = cu; kidx = cm; }
                maxu = __reduce_max_sync(FULL, holder ? ku : 0u);
            }
        }
        while (bal1) {                        // then group 1 (m0+32)
            const int src = __ffs(bal1) - 1;
            bal1 &= bal1 - 1;
            unsigned cu = __shfl_sync(FULL, u1, src);
            unsigned cm = (unsigned)(step * 64 + 32 + src);
            if (cu < maxu) {
                bool ismax = holder && (ku == maxu);
                unsigned emx = __reduce_max_sync(FULL, ismax ? kidx : 0u);
                if (ismax && kidx == emx) { ku = cu; kidx = cm; }
                maxu = __reduce_max_sync(FULL, holder ? ku : 0u);
            }
        }
    }

    // identify self = min key, lowest idx among exact ties (sorted column 0)
    unsigned minu = __reduce_min_sync(FULL, holder ? ku : 0xFFFFFFFFu);
    bool ismin = holder && (ku == minu);
    unsigned mni = __reduce_min_sync(FULL, ismin ? kidx : 0xFFFFFFFFu);
    bool keep = holder && !(ismin && kidx == mni);

    // mean of neighbor xyz (16 keepers)
    float4 pN = make_float4(0.f, 0.f, 0.f, 0.f);
    if (keep) pN = sp[kidx];
    float sx = pN.x, sy = pN.y, sz = pN.z;
#pragma unroll
    for (int o = 16; o > 0; o >>= 1) {
        sx += __shfl_xor_sync(FULL, sx, o);
        sy += __shfl_xor_sync(FULL, sy, o);
        sz += __shfl_xor_sync(FULL, sz, o);
    }
    if (lane == 0) {
        const float inv = 1.0f / (float)KK;
        size_t ob = ((size_t)b * NN + n) * OUTC;
        out[ob + 0] = sx * inv - q.x;
        out[ob + 1] = sy * inv - q.y;
        out[ob + 2] = sz * inv - q.z;
    }

    // emit knn indices (order within row irrelevant: gather sums them)
    unsigned kb = __ballot_sync(FULL, keep);
    int pos = __popc(kb & ((1u << lane) - 1u));
    if (keep) g_knn[((size_t)b * NN + n) * KK + pos] = (int)kidx;
}

// ---------------------------------------------------------------------------
// Kernel B: feature gather + mean - self, fp16x2 channel pairing (R12 exact).
// Block covers 32 channels: SMEM row c (0..15) holds half2(ch c0+c, ch c0+c+16)
// for all 2048 points, pitch 2049 -> the 16 channel lanes of a group hit banks
// (c + idx) % 32, conflict-free. One LDS gather feeds TWO output channels.
// ---------------------------------------------------------------------------
#define CTP    32           // channels per block (16 half2 rows)
#define PITCH  2049
#define SMEMB  (16 * PITCH * (int)sizeof(__half2))

__global__ __launch_bounds__(1024)
void gather_kernel(const float* __restrict__ features, float* __restrict__ out)
{
    extern __shared__ __half2 fsm[];   // [16][PITCH]

    const int b   = blockIdx.y;
    const int c0  = blockIdx.x * CTP;
    const int tid = threadIdx.x;

    // Stage: pack channels (c0+c, c0+c+16) as half2 rows
    const float* fbase = features + ((size_t)b * CC + c0) * NN;
    for (int i = tid; i < 16 * NN; i += 1024) {
        int c = i >> 11;          // 0..15
        int m = i & (NN - 1);
        float v0 = fbase[(size_t)c * NN + m];
        float v1 = fbase[(size_t)(c + 16) * NN + m];
        fsm[c * PITCH + m] = __floats2half2_rn(v0, v1);
    }
    __syncthreads();

    const int c  = tid & 15;      // half2 row
    const int n0 = tid >> 4;      // 0..63

    const int*     knn_b = g_knn + (size_t)b * NN * KK;
    const __half2* frow  = fsm + c * PITCH;
    float* outc = out + (size_t)b * NN * OUTC + 3 + c0 + c;

#pragma unroll 2
    for (int n = n0; n < NN; n += 64) {
        const int4* kr = (const int4*)(knn_b + n * KK);
        int4 k0 = __ldg(kr + 0);
        int4 k1 = __ldg(kr + 1);
        int4 k2 = __ldg(kr + 2);
        int4 k3 = __ldg(kr + 3);

        float2 a0 = __half22float2(frow[k0.x]);
        float2 a1 = __half22float2(frow[k0.y]);
        float2 a2 = __half22float2(frow[k0.z]);
        float2 a3 = __half22float2(frow[k0.w]);
        float2 a4 = __half22float2(frow[k1.x]);
        float2 a5 = __half22float2(frow[k1.y]);
        float2 a6 = __half22float2(frow[k1.z]);
        float2 a7 = __half22float2(frow[k1.w]);
        float s0 = a0.x + a1.x + a2.x + a3.x + a4.x + a5.x + a6.x + a7.x;
        float s1 = a0.y + a1.y + a2.y + a3.y + a4.y + a5.y + a6.y + a7.y;
        a0 = __half22float2(frow[k2.x]);
        a1 = __half22float2(frow[k2.y]);
        a2 = __half22float2(frow[k2.z]);
        a3 = __half22float2(frow[k2.w]);
        a4 = __half22float2(frow[k3.x]);
        a5 = __half22float2(frow[k3.y]);
        a6 = __half22float2(frow[k3.z]);
        a7 = __half22float2(frow[k3.w]);
        s0 += a0.x + a1.x + a2.x + a3.x + a4.x + a5.x + a6.x + a7.x;
        s1 += a0.y + a1.y + a2.y + a3.y + a4.y + a5.y + a6.y + a7.y;

        float2 self = __half22float2(frow[n]);
        float* o = outc + (size_t)n * OUTC;
        o[0]  = s0 * (1.0f / (float)KK) - self.x;
        o[16] = s1 * (1.0f / (float)KK) - self.y;
    }
}

// ---------------------------------------------------------------------------
extern "C" void kernel_launch(void* const* d_in, const int* in_sizes, int n_in,
                              void* d_out, int out_size)
{
    const float* xyz      = (const float*)d_in[0];
    const float* features = (const float*)d_in[1];
    float* out = (float*)d_out;

    knn_kernel<<<dim3(NN / QW, BB), 512>>>(xyz, out);

    cudaFuncSetAttribute(gather_kernel,
                         cudaFuncAttributeMaxDynamicSharedMemorySize, SMEMB);
    gather_kernel<<<dim3(CC / CTP, BB), 1024, SMEMB>>>(features, out);
}

// round 16
// speedup vs baseline: 1.5618x; 1.0016x over previous
#include <cuda_runtime.h>
#include <cuda_fp16.h>
#include <stdint.h>

// Problem constants (fixed by the dataset)
#define BB   16
#define NN   2048
#define CC   256
#define KK   16
#define KP1  17
#define OUTC 259   // 3 + C

// Scratch for knn indices (device global: allocation-free)
__device__ int g_knn[BB * NN * KK];

// order-preserving fp32 -> u32 map
__device__ __forceinline__ unsigned f2u(float f) {
    unsigned u = __float_as_uint(f);
    return u ^ (((unsigned)((int)u >> 31)) | 0x80000000u);
}

#define FULL 0xffffffffu

// ---------------------------------------------------------------------------
// Kernel A: warp-per-query exact top-17 (R12 structure, 16 queries/block).
// Ranking key: d2' = |p|^2 - 2 q.p  (the per-query constant |q|^2 is dropped;
// it cannot change per-query ordering). 17 best (u32 sortable key, idx) live
// one-per-lane on lanes 0..16. Each iteration scans 64 candidates (2/lane);
// ballots processed serially in ascending m, warp-uniform. Eviction: among
// holders with key == max, evict largest idx (top_k tie semantics); strict
// accept keeps incumbents on boundary ties. (key, idx) unique -> single
// eviction always. Self = lex-min pair == reference's sorted column 0.
// ---------------------------------------------------------------------------
#define QW 16   // queries (warps) per block -> 512 threads
__global__ __launch_bounds__(512)
void knn_kernel(const float* __restrict__ xyz, float* __restrict__ out)
{
    __shared__ float4 sp[NN];   // 32 KB: x, y, z, |p|^2

    const int b    = blockIdx.y;
    const int tid  = threadIdx.x;
    const int lane = tid & 31;
    const int warp = tid >> 5;
    const float* xb = xyz + (size_t)b * NN * 3;

    for (int m = tid; m < NN; m += 512) {
        float x = xb[m * 3 + 0];
        float y = xb[m * 3 + 1];
        float z = xb[m * 3 + 2];
        sp[m] = make_float4(x, y, z, x * x + y * y + z * z);
    }
    __syncthreads();

    const int n = blockIdx.x * QW + warp;     // this warp's query
    const float4 q = sp[n];

    const bool holder = (lane < KP1);
    // distinct huge sentinels (real u keys are far below 0xFFFFFF00)
    unsigned ku   = holder ? (0xFFFFFF00u | (unsigned)lane) : 0u;
    unsigned kidx = 0u;
    unsigned maxu = 0xFFFFFF00u | (KP1 - 1);  // current 17th (max of holders)

    for (int step = 0; step < NN / 64; step++) {
        const int m0 = step * 64 + lane;
        float4 p0 = sp[m0];                   // 2 independent LDS.128 chains
        float4 p1 = sp[m0 + 32];
        float dot0 = p0.x * q.x + p0.y * q.y + p0.z * q.z;
        float dot1 = p1.x * q.x + p1.y * q.y + p1.z * q.z;
        float d20  = fmaf(-2.0f, dot0, p0.w); // |p|^2 - 2 q.p (constant shift)
        float d21  = fmaf(-2.0f, dot1, p1.w);
        unsigned u0 = f2u(d20);
        unsigned u1 = f2u(d21);

        unsigned bal0 = __ballot_sync(FULL, u0 < maxu);
        unsigned bal1 = __ballot_sync(FULL, u1 < maxu);

        while (bal0) {                        // ascending m within group 0
            const int src = __ffs(bal0) - 1;
            bal0 &= bal0 - 1;
            unsigned cu = __shfl_sync(FULL, u0, src);
            unsigned cm = (unsigned)(step * 64 + src);
            if (cu < maxu) {                  // strict: boundary tie -> reject
                bool ismax = holder && (ku == maxu);
                unsigned emx = __reduce_max_sync(FULL, ismax ? kidx : 0u);
                if (ismax && kidx == emx) { ku = cu; kidx = cm; }
                maxu = __reduce_max_sync(FULL, holder ? ku : 0u);
            }
        }
        while (bal1) {                        // then group 1 (m0+32)
            const int src = __ffs(bal1) - 1;
            bal1 &= bal1 - 1;
            unsigned cu = __shfl_sync(FULL, u1, src);
            unsigned cm = (unsigned)(step * 64 + 32 + src);
            if (cu < maxu) {
                bool ismax = holder && (ku == maxu);
                unsigned emx = __reduce_max_sync(FULL, ismax ? kidx : 0u);
                if (ismax && kidx == emx) { ku = cu; kidx = cm; }
                maxu = __reduce_max_sync(FULL, holder ? ku : 0u);
            }
        }
    }

    // identify self = min key, lowest idx among exact ties (sorted column 0)
    unsigned minu = __reduce_min_sync(FULL, holder ? ku : 0xFFFFFFFFu);
    bool ismin = holder && (ku == minu);
    unsigned mni = __reduce_min_sync(FULL, ismin ? kidx : 0xFFFFFFFFu);
    bool keep = holder && !(ismin && kidx == mni);

    // mean of neighbor xyz (16 keepers)
    float4 pN = make_float4(0.f, 0.f, 0.f, 0.f);
    if (keep) pN = sp[kidx];
    float sx = pN.x, sy = pN.y, sz = pN.z;
#pragma unroll
    for (int o = 16; o > 0; o >>= 1) {
        sx += __shfl_xor_sync(FULL, sx, o);
        sy += __shfl_xor_sync(FULL, sy, o);
        sz += __shfl_xor_sync(FULL, sz, o);
    }
    if (lane == 0) {
        const float inv = 1.0f / (float)KK;
        size_t ob = ((size_t)b * NN + n) * OUTC;
        out[ob + 0] = sx * inv - q.x;
        out[ob + 1] = sy * inv - q.y;
        out[ob + 2] = sz * inv - q.z;
    }

    // emit knn indices (order within row irrelevant: gather sums them)
    unsigned kb = __ballot_sync(FULL, keep);
    int pos = __popc(kb & ((1u << lane) - 1u));
    if (keep) g_knn[((size_t)b * NN + n) * KK + pos] = (int)kidx;
}

// ---------------------------------------------------------------------------
// Kernel B: feature gather + mean - self, fp16x2 channel pairing (R12 exact).
// Block covers 32 channels: SMEM row c (0..15) holds half2(ch c0+c, ch c0+c+16)
// for all 2048 points, pitch 2049 -> the 16 channel lanes of a group hit banks
// (c + idx) % 32, conflict-free. One LDS gather feeds TWO output channels.
// ---------------------------------------------------------------------------
#define CTP    32           // channels per block (16 half2 rows)
#define PITCH  2049
#define SMEMB  (16 * PITCH * (int)sizeof(__half2))

__global__ __launch_bounds__(1024)
void gather_kernel(const float* __restrict__ features, float* __restrict__ out)
{
    extern __shared__ __half2 fsm[];   // [16][PITCH]

    const int b   = blockIdx.y;
    const int c0  = blockIdx.x * CTP;
    const int tid = threadIdx.x;

    // Stage: pack channels (c0+c, c0+c+16) as half2 rows
    const float* fbase = features + ((size_t)b * CC + c0) * NN;
    for (int i = tid; i < 16 * NN; i += 1024) {
        int c = i >> 11;          // 0..15
        int m = i & (NN - 1);
        float v0 = fbase[(size_t)c * NN + m];
        float v1 = fbase[(size_t)(c + 16) * NN + m];
        fsm[c * PITCH + m] = __floats2half2_rn(v0, v1);
    }
    __syncthreads();

    const int c  = tid & 15;      // half2 row
    const int n0 = tid >> 4;      // 0..63

    const int*     knn_b = g_knn + (size_t)b * NN * KK;
    const __half2* frow  = fsm + c * PITCH;
    float* outc = out + (size_t)b * NN * OUTC + 3 + c0 + c;

#pragma unroll 2
    for (int n = n0; n < NN; n += 64) {
        const int4* kr = (const int4*)(knn_b + n * KK);
        int4 k0 = __ldg(kr + 0);
        int4 k1 = __ldg(kr + 1);
        int4 k2 = __ldg(kr + 2);
        int4 k3 = __ldg(kr + 3);

        float2 a0 = __half22float2(frow[k0.x]);
        float2 a1 = __half22float2(frow[k0.y]);
        float2 a2 = __half22float2(frow[k0.z]);
        float2 a3 = __half22float2(frow[k0.w]);
        float2 a4 = __half22float2(frow[k1.x]);
        float2 a5 = __half22float2(frow[k1.y]);
        float2 a6 = __half22float2(frow[k1.z]);
        float2 a7 = __half22float2(frow[k1.w]);
        float s0 = a0.x + a1.x + a2.x + a3.x + a4.x + a5.x + a6.x + a7.x;
        float s1 = a0.y + a1.y + a2.y + a3.y + a4.y + a5.y + a6.y + a7.y;
        a0 = __half22float2(frow[k2.x]);
        a1 = __half22float2(frow[k2.y]);
        a2 = __half22float2(frow[k2.z]);
        a3 = __half22float2(frow[k2.w]);
        a4 = __half22float2(frow[k3.x]);
        a5 = __half22float2(frow[k3.y]);
        a6 = __half22float2(frow[k3.z]);
        a7 = __half22float2(frow[k3.w]);
        s0 += a0.x + a1.x + a2.x + a3.x + a4.x + a5.x + a6.x + a7.x;
        s1 += a0.y + a1.y + a2.y + a3.y + a4.y + a5.y + a6.y + a7.y;

        float2 self = __half22float2(frow[n]);
        float* o = outc + (size_t)n * OUTC;
        o[0]  = s0 * (1.0f / (float)KK) - self.x;
        o[16] = s1 * (1.0f / (float)KK) - self.y;
    }
}

// ---------------------------------------------------------------------------
extern "C" void kernel_launch(void* const* d_in, const int* in_sizes, int n_in,
                              void* d_out, int out_size)
{
    const float* xyz      = (const float*)d_in[0];
    const float* features = (const float*)d_in[1];
    float* out = (float*)d_out;

    knn_kernel<<<dim3(NN / QW, BB), 512>>>(xyz, out);

    cudaFuncSetAttribute(gather_kernel,
                         cudaFuncAttributeMaxDynamicSharedMemorySize, SMEMB);
    gather_kernel<<<dim3(CC / CTP, BB), 1024, SMEMB>>>(features, out);
}